// round 16
// baseline (speedup 1.0000x reference)
#include <cuda_runtime.h>
#include <cuda_bf16.h>
#include <math.h>

#define BATCH 32
#define MAXPV 50
#define RULENUM 256
#define ED 128
#define NPV (BATCH*MAXPV)   // 1600
#define LDP 68               // uint2 pitch per row (hi,lo interleaved)

// dynamic smem (bytes): sBh 32768 | sBl 32768 | sA 34816 |
//                       sp2 2*3200 | yr2 2*2048 | scj2 2*256
#define SMEM_BYTES (32768 + 32768 + 64*LDP*8 + 6400 + 4096 + 512)

// ---------------- scratch (device globals; no allocations allowed) ----------
__device__ __align__(16) float g_pemb[NPV*ED];
__device__ __align__(16) float g_vemb[NPV*ED];
__device__ __align__(16) float g_remb[RULENUM*ED];
__device__ __align__(16) float g_propemb[RULENUM*ED];
__device__ __align__(16) float g_pa[NPV*ED];
__device__ __align__(16) float g_pb[NPV*ED];
__device__ __align__(16) float g_pc[NPV*ED];
__device__ __align__(16) float g_ra[RULENUM*ED];
__device__ __align__(16) float g_rb[RULENUM*ED];
__device__ __align__(16) float g_rc[RULENUM*ED];
__device__ __align__(16) float g_propa[RULENUM*ED];
__device__ float g_rulemask[RULENUM];
__device__ float g_regpart[RULENUM];
__device__ float g_scores[BATCH*RULENUM];
__device__ uint2 g_bfragh[4096];   // [c8][kt][lane] = (b0,b1) bf16x2 hi
__device__ uint2 g_bfragl[4096];   // lo

__device__ __forceinline__ unsigned bf2_bits(__nv_bfloat162 p){
    return *reinterpret_cast<unsigned*>(&p);
}

__device__ __forceinline__ void split_bf16x2(float x0, float x1, unsigned &hi, unsigned &lo){
    __nv_bfloat162 hp = __floats2bfloat162_rn(x0, x1);
    float r0 = x0 - __low2float(hp);
    float r1 = x1 - __high2float(hp);
    __nv_bfloat162 lp = __floats2bfloat162_rn(r0, r1);
    hi = bf2_bits(hp); lo = bf2_bits(lp);
}

__device__ __forceinline__ void mma_bf16(float* c,
    unsigned a0, unsigned a1, unsigned a2, unsigned a3,
    unsigned b0, unsigned b1)
{
    asm volatile(
        "mma.sync.aligned.m16n8k16.row.col.f32.bf16.bf16.f32 "
        "{%0,%1,%2,%3}, {%4,%5,%6,%7}, {%8,%9}, {%0,%1,%2,%3};"
        : "+f"(c[0]), "+f"(c[1]), "+f"(c[2]), "+f"(c[3])
        : "r"(a0), "r"(a1), "r"(a2), "r"(a3), "r"(b0), "r"(b1));
}

// ---------------- kernel 1: gather + l2 normalize (warp-per-row) ------------
// blocks [0,464): 8 warps x 1 row each, float4 per lane, shuffle-only reduce.
// blocks [464,480): fc6 -> bf16 hi/lo fragment tables (merged bfrag).
__global__ void __launch_bounds__(256) norm_gather_kernel(
    const int* __restrict__ prop, const int* __restrict__ val,
    const float* __restrict__ ent, const float* __restrict__ rule,
    const float* __restrict__ fc6w)
{
    if (blockIdx.x >= 464){
        int idx = (blockIdx.x - 464)*256 + threadIdx.x;   // 4096 total
        int c8 = idx >> 8, kt = (idx >> 5) & 7, lane = idx & 31;
        int gid = lane >> 2, tig = lane & 3;
        int col = c8*8 + gid;
        int k0 = kt*16 + 2*tig;
        unsigned h0,l0,h1,l1;
        split_bf16x2(fc6w[ k0   *ED + col], fc6w[(k0+1)*ED + col], h0, l0);
        split_bf16x2(fc6w[(k0+8)*ED + col], fc6w[(k0+9)*ED + col], h1, l1);
        g_bfragh[idx] = make_uint2(h0, h1);
        g_bfragl[idx] = make_uint2(l0, l1);
        return;
    }

    int row = blockIdx.x*8 + (threadIdx.x>>5);
    int lane = threadIdx.x & 31;
    const float* src; float* dst;
    if (row < NPV)            { src = ent + (size_t)prop[row]*ED;              dst = g_pemb + row*ED; }
    else if (row < 2*NPV)     { int t=row-NPV;   src = ent + (size_t)val[t]*ED; dst = g_vemb + t*ED; }
    else if (row < 2*NPV+256) { int t=row-2*NPV; src = rule + t*ED;            dst = g_remb + t*ED; }
    else                      { int t=row-2*NPV-256; src = ent + (size_t)t*ED; dst = g_propemb + t*ED; }

    float4 x = reinterpret_cast<const float4*>(src)[lane];
    float s = x.x*x.x + x.y*x.y + x.z*x.z + x.w*x.w;
    #pragma unroll
    for (int o=16;o>0;o>>=1) s += __shfl_xor_sync(0xffffffffu, s, o);
    float inv = 1.f / fmaxf(sqrtf(s), 1e-12f);
    float4 y; y.x = x.x*inv; y.y = x.y*inv; y.z = x.z*inv; y.w = x.w*inv;
    reinterpret_cast<float4*>(dst)[lane] = y;
}

// ---------------- kernel 2: all small 128x128 GEMMs, 16-row tiles -----------
__global__ void __launch_bounds__(128) small_gemm_kernel(
    const float* __restrict__ fc1w, const float* __restrict__ fc1b,
    const float* __restrict__ fc2w, const float* __restrict__ fc2b,
    const float* __restrict__ fc3w, const float* __restrict__ fc3b)
{
    int blk = blockIdx.x, k = threadIdx.x;
    const float *in, *W; const float* bias = nullptr; float* out;
    if (blk < 300){                      // pa/pb/pc: 3 x 100 blocks x 16 rows
        int seg = blk/100, rb = (blk%100)*16;
        in = g_pemb + rb*ED;
        W   = seg==0 ? fc1w : (seg==1 ? fc2w : fc3w);
        out = (seg==0 ? g_pa : (seg==1 ? g_pb : g_pc)) + rb*ED;
    } else {                             // ra/rb/rc/propa: 4 x 16 blocks
        int q = blk - 300;
        int seg = q/16, rb = (q%16)*16;
        if (seg < 3){
            in  = g_remb + rb*ED;
            W   = (seg==0 ? fc1w : (seg==1 ? fc2w : fc3w)) + ED*ED;
            bias= (seg==0 ? fc1b : (seg==1 ? fc2b : fc3b));
            out = (seg==0 ? g_ra : (seg==1 ? g_rb : g_rc)) + rb*ED;
        } else {
            in = g_propemb + rb*ED;  W = fc1w;  out = g_propa + rb*ED;
        }
    }

    __shared__ __align__(16) float4 ins[16][32];   // 16 rows x 128 floats
    const float4* in4 = reinterpret_cast<const float4*>(in);
    #pragma unroll
    for (int i=k; i<512; i+=128) ins[i>>5][i&31] = in4[i];
    __syncthreads();

    float acc[16];
    float bv = bias ? bias[k] : 0.f;
    #pragma unroll
    for (int r=0;r<16;r++) acc[r] = bv;

    #pragma unroll 4
    for (int q=0; q<32; q++){
        float w0 = __ldg(W + (4*q  )*ED + k);
        float w1 = __ldg(W + (4*q+1)*ED + k);
        float w2 = __ldg(W + (4*q+2)*ED + k);
        float w3 = __ldg(W + (4*q+3)*ED + k);
        #pragma unroll
        for (int r=0;r<16;r++){
            float4 iv = ins[r][q];
            acc[r] = fmaf(iv.x, w0, acc[r]);
            acc[r] = fmaf(iv.y, w1, acc[r]);
            acc[r] = fmaf(iv.z, w2, acc[r]);
            acc[r] = fmaf(iv.w, w3, acc[r]);
        }
    }
    #pragma unroll
    for (int r=0;r<16;r++) out[r*ED + k] = acc[r];
}

// ---------------- kernel 3: pi matrix (512 thr: 16 warps x 16 props) --------
__global__ void pi_kernel(const float* __restrict__ fc4w, const float* __restrict__ fc4b)
{
    int r = blockIdx.x;
    int tid = threadIdx.x, lane = tid&31, w = tid>>5;   // 16 warps
    __shared__ float rarow[ED], f4s[ED];
    if (tid < ED){ rarow[tid] = g_ra[r*ED+tid]; f4s[tid] = fc4w[tid]; }
    __syncthreads();
    float fb4 = fc4b[0];
    float mask_s = 0.f, reg_s = 0.f;
    for (int pp=0; pp<16; pp++){
        int p = w*16 + pp;
        float s = 0.f;
        #pragma unroll
        for (int q=0;q<4;q++){
            int i = lane*4 + q;
            float h = fmaxf(g_propa[p*ED + i] + rarow[i], 0.f);
            s = fmaf(h, f4s[i], s);
        }
        #pragma unroll
        for (int o=16;o>0;o>>=1) s += __shfl_xor_sync(0xffffffffu, s, o);
        if (lane==0){
            float piv = 1.f/(1.f+expf(-(s+fb4)));
            if (piv > 0.5f) mask_s += piv;
            float diag = (r==p) ? 1.f : 0.f;
            float rv = piv*diag + (1.f-piv)*(1.f-diag);
            reg_s += -logf(rv + 1e-8f) * ((1.f-diag) + diag*(float)RULENUM);
        }
    }
    __shared__ float ms[16], rs[16];
    if (lane==0){ ms[w]=mask_s; rs[w]=reg_s; }
    __syncthreads();
    if (tid==0){
        float m=0.f, rg=0.f;
        #pragma unroll
        for (int i=0;i<16;i++){ m+=ms[i]; rg+=rs[i]; }
        g_rulemask[r] = m + 1.f;
        g_regpart[r]  = rg;
    }
}

// ---------------- kernel 4: main scoring, bf16x3 tensor GEMM ----------------
// grid (256, 4), 256 threads (8 warps), 2 CTAs/SM. Block owns rule r and 8
// batches. Warp (mg=w&1, ng=w>>1) owns rows [32mg,+32) x cols [32ng,+32).
// THREE bars per batch: sp/yred/scj double-buffered -> end-of-loop bar gone
// (A(b+1) sA writes are fenced by the yred bar; other buffers alternate).
__global__ void __launch_bounds__(256, 2) main_kernel(
    const int* __restrict__ samemask, const int* __restrict__ padmask,
    const float* __restrict__ fc4w, const float* __restrict__ fc4b,
    const float* __restrict__ fc5w, const float* __restrict__ fc5b,
    const float* __restrict__ fc6b)
{
    extern __shared__ unsigned char smraw[];
    uint2*  sBh  = reinterpret_cast<uint2*>(smraw);
    uint2*  sBl  = sBh + 4096;
    uint2*  sA   = sBl + 4096;                       // [64*LDP]
    float2* sp2  = reinterpret_cast<float2*>(sA + 64*LDP);  // [2][50*8]
    float2* yr2  = sp2 + 2*50*8;                     // [2][64*4]
    float*  scj2 = reinterpret_cast<float*>(yr2 + 2*64*4);  // [2][64]

    int r = blockIdx.x;
    int t = threadIdx.x, lane = t&31, w = t>>5;
    int gid = lane>>2, tig = lane&3;
    int mg = w & 1, ng = w >> 1;          // ng in 0..3: cols [32ng, 32ng+32)
    int cb = ng*32;

    // ---- copy fc6 frag tables into shared; zero A pad rows ----
    for (int i=t; i<4096; i+=256){ sBh[i] = g_bfragh[i]; sBl[i] = g_bfragl[i]; }
    for (int i=t; i<14*LDP; i+=256) sA[50*LDP + i] = make_uint2(0u,0u);

    // ---- A-phase constants: thread owns k-pair kk2, j stream jsel (0..3) ----
    int kk2 = t & 63, jsel = t >> 6;
    int k2 = kk2*2;
    int wp = (t>>5) & 1;                  // which of the 2 warps sharing jsel
    float2 ra2 = *reinterpret_cast<const float2*>(&g_ra[r*ED + k2]);
    float2 rb2 = *reinterpret_cast<const float2*>(&g_rb[r*ED + k2]);
    float2 rc2 = *reinterpret_cast<const float2*>(&g_rc[r*ED + k2]);
    float2 f42 = *reinterpret_cast<const float2*>(&fc4w[k2]);
    float2 f52 = *reinterpret_cast<const float2*>(&fc5w[k2]);
    const float2* pa2 = reinterpret_cast<const float2*>(g_pa);
    const float2* pb2 = reinterpret_cast<const float2*>(g_pb);
    const float2* pc2 = reinterpret_cast<const float2*>(g_pc);

    float fb4 = fc4b[0], fb5 = fc5b[0];
    float rminv = 1.f / g_rulemask[r];
    float b6v[4][2];
    #pragma unroll
    for (int nt=0; nt<4; nt++){
        b6v[nt][0] = fc6b[cb + nt*8 + tig*2];
        b6v[nt][1] = fc6b[cb + nt*8 + tig*2 + 1];
    }

    #pragma unroll 1
    for (int bi=0; bi<8; bi++){
        int b = blockIdx.y*8 + bi;
        int cur = bi & 1;
        float2* sp   = sp2 + cur*50*8;
        float2* yred = yr2 + cur*64*4;
        float*  scj  = scj2 + cur*64;

        // ---- Phase A: batched-prefetch h1/h2/h3; h3 -> (hi,lo) uint2 plane --
        #pragma unroll 1
        for (int i0=0; i0<13; i0+=4){
            float2 la[4], lb[4], lc[4];
            #pragma unroll
            for (int q=0;q<4;q++){
                int i = i0+q;
                int j = i*4 + jsel;
                if (i < 13 && j < MAXPV){
                    int base = (b*MAXPV + j)*64 + kk2;
                    la[q] = pa2[base]; lb[q] = pb2[base]; lc[q] = pc2[base];
                }
            }
            #pragma unroll
            for (int q=0;q<4;q++){
                int i = i0+q;
                int j = i*4 + jsel;
                if (i < 13 && j < MAXPV){
                    float h1a = fmaxf(la[q].x + ra2.x, 0.f), h1b = fmaxf(la[q].y + ra2.y, 0.f);
                    float h2a = fmaxf(lb[q].x + rb2.x, 0.f), h2b = fmaxf(lb[q].y + rb2.y, 0.f);
                    float h3a = fmaxf(lc[q].x + rc2.x, 0.f), h3b = fmaxf(lc[q].y + rc2.y, 0.f);
                    unsigned hp, lp;
                    split_bf16x2(h3a, h3b, hp, lp);
                    sA[j*LDP + kk2] = make_uint2(hp, lp);
                    float u  = h1a*f42.x + h1b*f42.y;
                    float qq = h2a*f52.x + h2b*f52.y;
                    #pragma unroll
                    for (int o=16;o>=4;o>>=1){
                        u  += __shfl_xor_sync(0xffffffffu, u,  o);
                        qq += __shfl_xor_sync(0xffffffffu, qq, o);
                    }
                    if (lane < 4) sp[j*8 + wp*4 + lane] = make_float2(u, qq);
                }
            }
        }
        __syncthreads();   // bar1: sA + sp(cur) published (and sB on bi==0)

        // ---- Phase B: K=128 (8 kt), warp tile 32 rows x 32 cols ----
        float C[2][4][4];
        #pragma unroll
        for (int ml=0;ml<2;ml++)
            #pragma unroll
            for (int nt=0;nt<4;nt++)
                #pragma unroll
                for (int q=0;q<4;q++) C[ml][nt][q] = 0.f;

        #pragma unroll
        for (int kt=0; kt<8; kt++){
            int p0 = kt*8 + tig;
            uint2 A0[2], A1[2], A2[2], A3[2];
            #pragma unroll
            for (int ml=0; ml<2; ml++){
                int row = (mg*2+ml)*16 + gid;
                A0[ml] = sA[ row   *LDP + p0  ];
                A1[ml] = sA[(row+8)*LDP + p0  ];
                A2[ml] = sA[ row   *LDP + p0+4];
                A3[ml] = sA[(row+8)*LDP + p0+4];
            }
            #pragma unroll
            for (int nt=0; nt<4; nt++){
                int idx = (ng*4+nt)*256 + kt*32 + lane;
                uint2 BH = sBh[idx];
                uint2 BL = sBl[idx];
                #pragma unroll
                for (int ml=0; ml<2; ml++){
                    mma_bf16(C[ml][nt], A0[ml].x,A1[ml].x,A2[ml].x,A3[ml].x, BH.x, BH.y);
                    mma_bf16(C[ml][nt], A0[ml].x,A1[ml].x,A2[ml].x,A3[ml].x, BL.x, BL.y);
                    mma_bf16(C[ml][nt], A0[ml].y,A1[ml].y,A2[ml].y,A3[ml].y, BH.x, BH.y);
                }
            }
        }

        // ---- Phase C: per-row y^2 and y.v partials (warp's 32 cols) ----
        #pragma unroll
        for (int ml=0; ml<2; ml++){
            int rowA = (mg*2+ml)*16 + gid;
            int rowB = rowA + 8;
            float yyA=0.f, yvA=0.f, yyB=0.f, yvB=0.f;
            #pragma unroll
            for (int nt=0; nt<4; nt++){
                int col0 = cb + nt*8 + tig*2;
                float y0 = C[ml][nt][0] + b6v[nt][0];
                float y1 = C[ml][nt][1] + b6v[nt][1];
                float y2 = C[ml][nt][2] + b6v[nt][0];
                float y3 = C[ml][nt][3] + b6v[nt][1];
                float v0=0.f, v1=0.f, v2=0.f, v3=0.f;
                if (rowA < MAXPV){
                    float2 vv = *reinterpret_cast<const float2*>(&g_vemb[(b*MAXPV+rowA)*ED + col0]);
                    v0 = vv.x; v1 = vv.y;
                }
                if (rowB < MAXPV){
                    float2 vv = *reinterpret_cast<const float2*>(&g_vemb[(b*MAXPV+rowB)*ED + col0]);
                    v2 = vv.x; v3 = vv.y;
                }
                yyA += y0*y0 + y1*y1;  yvA += y0*v0 + y1*v1;
                yyB += y2*y2 + y3*y3;  yvB += y2*v2 + y3*v3;
            }
            #pragma unroll
            for (int o=1;o<=2;o<<=1){
                yyA += __shfl_xor_sync(0xffffffffu, yyA, o);
                yvA += __shfl_xor_sync(0xffffffffu, yvA, o);
                yyB += __shfl_xor_sync(0xffffffffu, yyB, o);
                yvB += __shfl_xor_sync(0xffffffffu, yvB, o);
            }
            if (tig == 0){
                yred[rowA*4 + ng] = make_float2(yyA, yvA);
                yred[rowB*4 + ng] = make_float2(yyB, yvB);
            }
        }
        __syncthreads();   // bar2: yred(cur) published; sA free for next A

        // ---- scoring ----
        if (t < MAXPV){
            float s1d=0.f, pd=0.f, yn2=0.f, ydv=0.f;
            #pragma unroll
            for (int i=0;i<8;i++){
                float2 q1 = sp[t*8 + i];
                s1d += q1.x; pd += q1.y;
            }
            #pragma unroll
            for (int i=0;i<4;i++){
                float2 q2 = yred[t*4 + i];
                yn2 += q2.x; ydv += q2.y;
            }
            float s1 = 1.f/(1.f+expf(-(s1d+fb4)));
            float p  = 1.f/(1.f+expf(-(pd +fb5)));
            float yn = sqrtf(yn2);
            float cosv = ydv / fmaxf(yn, 1e-8f);   // v_emb unit-norm; gv = y/||y||
            float s2 = 0.5f*cosv + 0.5f;
            float sc = p + (1.f-p)*s2;
            sc = (samemask[b*MAXPV+t]==1) ? (s1*sc) : (1.f - s1);
            sc *= (float)padmask[b*MAXPV+t];
            if (!(s1 > 0.5f)) sc = 0.f;
            scj[t] = sc;
        }
        __syncthreads();   // bar3: scj(cur) published
        if (t < 32){
            float s = scj[t];
            if (t + 32 < MAXPV) s += scj[t+32];
            #pragma unroll
            for (int o=16;o>0;o>>=1) s += __shfl_xor_sync(0xffffffffu, s, o);
            if (t==0) g_scores[b*RULENUM + r] = s * rminv;
        }
        // no end bar: next A writes sA (fenced by bar2) and the OTHER
        // sp/yred/scj buffer; the summing warp's scj(cur) reads complete
        // before it participates in the next iteration's bar1.
    }
}

// ---------------- kernel 5: deterministic finalize ---------------------------
__global__ void finalize_kernel(float* __restrict__ out, int out_size)
{
    int tid = threadIdx.x, lane = tid&31, w = tid>>5;  // 256 threads, 8 warps
    float rg = g_regpart[tid];
    #pragma unroll
    for (int o=16;o>0;o>>=1) rg += __shfl_xor_sync(0xffffffffu, rg, o);
    __shared__ float rs[8];
    if (lane==0) rs[w] = rg;
    __syncthreads();
    if (tid==0 && out_size > BATCH){
        float t=0.f;
        #pragma unroll
        for (int i=0;i<8;i++) t += rs[i];
        out[BATCH] = t / (float)(RULENUM*RULENUM);
    }
    #pragma unroll
    for (int q=0;q<4;q++){
        int b = w*4 + q;
        float m = -1e30f;
        for (int c=lane;c<RULENUM;c+=32) m = fmaxf(m, g_scores[b*RULENUM+c]);
        #pragma unroll
        for (int o=16;o>0;o>>=1) m = fmaxf(m, __shfl_xor_sync(0xffffffffu, m, o));
        if (lane==0 && b < out_size) out[b] = m;
    }
}

// ---------------- launch -----------------------------------------------------
extern "C" void kernel_launch(void* const* d_in, const int* in_sizes, int n_in,
                              void* d_out, int out_size)
{
    const int*   prop = (const int*)d_in[0];
    const int*   val  = (const int*)d_in[1];
    const int*   same = (const int*)d_in[2];
    const int*   pad  = (const int*)d_in[3];
    const float* rule = (const float*)d_in[4];
    const float* ent  = (const float*)d_in[5];
    const float* fc1w = (const float*)d_in[6];
    const float* fc1b = (const float*)d_in[7];
    const float* fc2w = (const float*)d_in[8];
    const float* fc2b = (const float*)d_in[9];
    const float* fc3w = (const float*)d_in[10];
    const float* fc3b = (const float*)d_in[11];
    const float* fc4w = (const float*)d_in[12];
    const float* fc4b = (const float*)d_in[13];
    const float* fc5w = (const float*)d_in[14];
    const float* fc5b = (const float*)d_in[15];
    const float* fc6w = (const float*)d_in[16];
    const float* fc6b = (const float*)d_in[17];

    cudaFuncSetAttribute(main_kernel,
                         cudaFuncAttributeMaxDynamicSharedMemorySize, SMEM_BYTES);

    norm_gather_kernel<<<480, 256>>>(prop, val, ent, rule, fc6w);
    small_gemm_kernel<<<364, 128>>>(fc1w, fc1b, fc2w, fc2b, fc3w, fc3b);
    pi_kernel<<<RULENUM, 512>>>(fc4w, fc4b);
    main_kernel<<<dim3(RULENUM, 4), 256, SMEM_BYTES>>>(same, pad, fc4w, fc4b,
                                                       fc5w, fc5b, fc6b);
    finalize_kernel<<<1, 256>>>((float*)d_out, out_size);
}

// round 17
// speedup vs baseline: 1.1034x; 1.1034x over previous
#include <cuda_runtime.h>
#include <cuda_bf16.h>
#include <math.h>

#define BATCH 32
#define MAXPV 50
#define RULENUM 256
#define ED 128
#define NPV (BATCH*MAXPV)   // 1600
#define LDP 68               // uint2 pitch per row (hi,lo interleaved)

// dynamic smem (bytes): sBh 32768 | sBl 32768 | sA 34816 |
//                       sp 3200 | yred 2048 | scj 256
#define SMEM_BYTES (32768 + 32768 + 64*LDP*8 + 3200 + 2048 + 256)

// ---------------- scratch (device globals; no allocations allowed) ----------
__device__ __align__(16) float g_pemb[NPV*ED];
__device__ __align__(16) float g_vemb[NPV*ED];
__device__ __align__(16) float g_remb[RULENUM*ED];
__device__ __align__(16) float g_propemb[RULENUM*ED];
__device__ __align__(16) float g_pa[NPV*ED];
__device__ __align__(16) float g_pb[NPV*ED];
__device__ __align__(16) float g_pc[NPV*ED];
__device__ __align__(16) float g_ra[RULENUM*ED];
__device__ __align__(16) float g_rb[RULENUM*ED];
__device__ __align__(16) float g_rc[RULENUM*ED];
__device__ __align__(16) float g_propa[RULENUM*ED];
__device__ float g_rulemask[RULENUM];
__device__ float g_regpart[RULENUM];
__device__ float g_scores[BATCH*RULENUM];   // UNNORMALIZED sums (divide in finalize)
__device__ uint2 g_bfragh[4096];   // [c8][kt][lane] = (b0,b1) bf16x2 hi
__device__ uint2 g_bfragl[4096];   // lo

__device__ __forceinline__ unsigned bf2_bits(__nv_bfloat162 p){
    return *reinterpret_cast<unsigned*>(&p);
}

__device__ __forceinline__ void split_bf16x2(float x0, float x1, unsigned &hi, unsigned &lo){
    __nv_bfloat162 hp = __floats2bfloat162_rn(x0, x1);
    float r0 = x0 - __low2float(hp);
    float r1 = x1 - __high2float(hp);
    __nv_bfloat162 lp = __floats2bfloat162_rn(r0, r1);
    hi = bf2_bits(hp); lo = bf2_bits(lp);
}

__device__ __forceinline__ void mma_bf16(float* c,
    unsigned a0, unsigned a1, unsigned a2, unsigned a3,
    unsigned b0, unsigned b1)
{
    asm volatile(
        "mma.sync.aligned.m16n8k16.row.col.f32.bf16.bf16.f32 "
        "{%0,%1,%2,%3}, {%4,%5,%6,%7}, {%8,%9}, {%0,%1,%2,%3};"
        : "+f"(c[0]), "+f"(c[1]), "+f"(c[2]), "+f"(c[3])
        : "r"(a0), "r"(a1), "r"(a2), "r"(a3), "r"(b0), "r"(b1));
}

// ---------------- kernel 1: gather + l2 normalize (warp-per-row) ------------
// blocks [0,464): 8 warps x 1 row each, float4 per lane, shuffle-only reduce.
// blocks [464,480): fc6 -> bf16 hi/lo fragment tables (merged bfrag).
__global__ void __launch_bounds__(256) norm_gather_kernel(
    const int* __restrict__ prop, const int* __restrict__ val,
    const float* __restrict__ ent, const float* __restrict__ rule,
    const float* __restrict__ fc6w)
{
    if (blockIdx.x >= 464){
        int idx = (blockIdx.x - 464)*256 + threadIdx.x;   // 4096 total
        int c8 = idx >> 8, kt = (idx >> 5) & 7, lane = idx & 31;
        int gid = lane >> 2, tig = lane & 3;
        int col = c8*8 + gid;
        int k0 = kt*16 + 2*tig;
        unsigned h0,l0,h1,l1;
        split_bf16x2(fc6w[ k0   *ED + col], fc6w[(k0+1)*ED + col], h0, l0);
        split_bf16x2(fc6w[(k0+8)*ED + col], fc6w[(k0+9)*ED + col], h1, l1);
        g_bfragh[idx] = make_uint2(h0, h1);
        g_bfragl[idx] = make_uint2(l0, l1);
        return;
    }

    int row = blockIdx.x*8 + (threadIdx.x>>5);
    int lane = threadIdx.x & 31;
    const float* src; float* dst;
    if (row < NPV)            { src = ent + (size_t)prop[row]*ED;              dst = g_pemb + row*ED; }
    else if (row < 2*NPV)     { int t=row-NPV;   src = ent + (size_t)val[t]*ED; dst = g_vemb + t*ED; }
    else if (row < 2*NPV+256) { int t=row-2*NPV; src = rule + t*ED;            dst = g_remb + t*ED; }
    else                      { int t=row-2*NPV-256; src = ent + (size_t)t*ED; dst = g_propemb + t*ED; }

    float4 x = reinterpret_cast<const float4*>(src)[lane];
    float s = x.x*x.x + x.y*x.y + x.z*x.z + x.w*x.w;
    #pragma unroll
    for (int o=16;o>0;o>>=1) s += __shfl_xor_sync(0xffffffffu, s, o);
    float inv = 1.f / fmaxf(sqrtf(s), 1e-12f);
    float4 y; y.x = x.x*inv; y.y = x.y*inv; y.z = x.z*inv; y.w = x.w*inv;
    reinterpret_cast<float4*>(dst)[lane] = y;
}

// ---------------- kernel 2: all small 128x128 GEMMs, 16-row tiles -----------
__global__ void __launch_bounds__(128) small_gemm_kernel(
    const float* __restrict__ fc1w, const float* __restrict__ fc1b,
    const float* __restrict__ fc2w, const float* __restrict__ fc2b,
    const float* __restrict__ fc3w, const float* __restrict__ fc3b)
{
    int blk = blockIdx.x, k = threadIdx.x;
    const float *in, *W; const float* bias = nullptr; float* out;
    if (blk < 300){                      // pa/pb/pc: 3 x 100 blocks x 16 rows
        int seg = blk/100, rb = (blk%100)*16;
        in = g_pemb + rb*ED;
        W   = seg==0 ? fc1w : (seg==1 ? fc2w : fc3w);
        out = (seg==0 ? g_pa : (seg==1 ? g_pb : g_pc)) + rb*ED;
    } else {                             // ra/rb/rc/propa: 4 x 16 blocks
        int q = blk - 300;
        int seg = q/16, rb = (q%16)*16;
        if (seg < 3){
            in  = g_remb + rb*ED;
            W   = (seg==0 ? fc1w : (seg==1 ? fc2w : fc3w)) + ED*ED;
            bias= (seg==0 ? fc1b : (seg==1 ? fc2b : fc3b));
            out = (seg==0 ? g_ra : (seg==1 ? g_rb : g_rc)) + rb*ED;
        } else {
            in = g_propemb + rb*ED;  W = fc1w;  out = g_propa + rb*ED;
        }
    }

    __shared__ __align__(16) float4 ins[16][32];   // 16 rows x 128 floats
    const float4* in4 = reinterpret_cast<const float4*>(in);
    #pragma unroll
    for (int i=k; i<512; i+=128) ins[i>>5][i&31] = in4[i];
    __syncthreads();

    float acc[16];
    float bv = bias ? bias[k] : 0.f;
    #pragma unroll
    for (int r=0;r<16;r++) acc[r] = bv;

    #pragma unroll 4
    for (int q=0; q<32; q++){
        float w0 = __ldg(W + (4*q  )*ED + k);
        float w1 = __ldg(W + (4*q+1)*ED + k);
        float w2 = __ldg(W + (4*q+2)*ED + k);
        float w3 = __ldg(W + (4*q+3)*ED + k);
        #pragma unroll
        for (int r=0;r<16;r++){
            float4 iv = ins[r][q];
            acc[r] = fmaf(iv.x, w0, acc[r]);
            acc[r] = fmaf(iv.y, w1, acc[r]);
            acc[r] = fmaf(iv.z, w2, acc[r]);
            acc[r] = fmaf(iv.w, w3, acc[r]);
        }
    }
    #pragma unroll
    for (int r=0;r<16;r++) out[r*ED + k] = acc[r];
}

// ---------------- kernel 4: fused main scoring + pi --------------------------
// grid (256, 9), 256 threads (8 warps), 2 CTAs/SM.
//  y < 8 : main — block owns rule r and 4 batches (R15-proven structure).
//          Scores stored UNNORMALIZED (rulemask division deferred to finalize),
//          which removes the pi -> main dependency.
//  y == 8: pi — rule_mask + reg partials for rule r (runs concurrently).
__global__ void __launch_bounds__(256, 2) main_kernel(
    const int* __restrict__ samemask, const int* __restrict__ padmask,
    const float* __restrict__ fc4w, const float* __restrict__ fc4b,
    const float* __restrict__ fc5w, const float* __restrict__ fc5b,
    const float* __restrict__ fc6b)
{
    extern __shared__ unsigned char smraw[];
    int r = blockIdx.x;
    int t = threadIdx.x, lane = t&31, w = t>>5;

    if (blockIdx.y == 8){
        // ---------------- pi branch: 8 warps x 32 props ----------------
        float* rarow = reinterpret_cast<float*>(smraw);
        float* f4s   = rarow + ED;
        if (t < ED){ rarow[t] = g_ra[r*ED+t]; f4s[t] = fc4w[t]; }
        __syncthreads();
        float fb4 = fc4b[0];
        float mask_s = 0.f, reg_s = 0.f;
        for (int pp=0; pp<32; pp++){
            int p = w*32 + pp;
            float s = 0.f;
            #pragma unroll
            for (int q=0;q<4;q++){
                int i = lane*4 + q;
                float h = fmaxf(g_propa[p*ED + i] + rarow[i], 0.f);
                s = fmaf(h, f4s[i], s);
            }
            #pragma unroll
            for (int o=16;o>0;o>>=1) s += __shfl_xor_sync(0xffffffffu, s, o);
            if (lane==0){
                float piv = 1.f/(1.f+expf(-(s+fb4)));
                if (piv > 0.5f) mask_s += piv;
                float diag = (r==p) ? 1.f : 0.f;
                float rv = piv*diag + (1.f-piv)*(1.f-diag);
                reg_s += -logf(rv + 1e-8f) * ((1.f-diag) + diag*(float)RULENUM);
            }
        }
        float* ms = f4s + ED; float* rs = ms + 8;
        if (lane==0){ ms[w]=mask_s; rs[w]=reg_s; }
        __syncthreads();
        if (t==0){
            float m=0.f, rg=0.f;
            #pragma unroll
            for (int i=0;i<8;i++){ m+=ms[i]; rg+=rs[i]; }
            g_rulemask[r] = m + 1.f;
            g_regpart[r]  = rg;
        }
        return;
    }

    // ---------------- main branch (R15 structure) ----------------
    uint2*  sBh  = reinterpret_cast<uint2*>(smraw);
    uint2*  sBl  = sBh + 4096;
    uint2*  sA   = sBl + 4096;                       // [64*LDP]
    float2* sp   = reinterpret_cast<float2*>(sA + 64*LDP);  // [50*8]
    float2* yred = sp + 50*8;                        // [64*4]
    float*  scj  = reinterpret_cast<float*>(yred + 64*4);

    int gid = lane>>2, tig = lane&3;
    int mg = w & 1, ng = w >> 1;          // ng in 0..3: cols [32ng, 32ng+32)
    int cb = ng*32;

    // ---- copy fc6 frag tables into shared; zero A pad rows ----
    for (int i=t; i<4096; i+=256){ sBh[i] = g_bfragh[i]; sBl[i] = g_bfragl[i]; }
    for (int i=t; i<14*LDP; i+=256) sA[50*LDP + i] = make_uint2(0u,0u);

    // ---- A-phase constants: thread owns k-pair kk2, j stream jsel (0..3) ----
    int kk2 = t & 63, jsel = t >> 6;
    int k2 = kk2*2;
    int wp = (t>>5) & 1;                  // which of the 2 warps sharing jsel
    float2 ra2 = *reinterpret_cast<const float2*>(&g_ra[r*ED + k2]);
    float2 rb2 = *reinterpret_cast<const float2*>(&g_rb[r*ED + k2]);
    float2 rc2 = *reinterpret_cast<const float2*>(&g_rc[r*ED + k2]);
    float2 f42 = *reinterpret_cast<const float2*>(&fc4w[k2]);
    float2 f52 = *reinterpret_cast<const float2*>(&fc5w[k2]);
    const float2* pa2 = reinterpret_cast<const float2*>(g_pa);
    const float2* pb2 = reinterpret_cast<const float2*>(g_pb);
    const float2* pc2 = reinterpret_cast<const float2*>(g_pc);

    float fb4 = fc4b[0], fb5 = fc5b[0];
    float b6v[4][2];
    #pragma unroll
    for (int nt=0; nt<4; nt++){
        b6v[nt][0] = fc6b[cb + nt*8 + tig*2];
        b6v[nt][1] = fc6b[cb + nt*8 + tig*2 + 1];
    }

    #pragma unroll 1
    for (int bi=0; bi<4; bi++){
        int b = blockIdx.y*4 + bi;

        // ---- Phase A: batched-prefetch h1/h2/h3; h3 -> (hi,lo) uint2 plane --
        #pragma unroll 1
        for (int i0=0; i0<13; i0+=4){
            float2 la[4], lb[4], lc[4];
            #pragma unroll
            for (int q=0;q<4;q++){
                int i = i0+q;
                int j = i*4 + jsel;
                if (i < 13 && j < MAXPV){
                    int base = (b*MAXPV + j)*64 + kk2;
                    la[q] = pa2[base]; lb[q] = pb2[base]; lc[q] = pc2[base];
                }
            }
            #pragma unroll
            for (int q=0;q<4;q++){
                int i = i0+q;
                int j = i*4 + jsel;
                if (i < 13 && j < MAXPV){
                    float h1a = fmaxf(la[q].x + ra2.x, 0.f), h1b = fmaxf(la[q].y + ra2.y, 0.f);
                    float h2a = fmaxf(lb[q].x + rb2.x, 0.f), h2b = fmaxf(lb[q].y + rb2.y, 0.f);
                    float h3a = fmaxf(lc[q].x + rc2.x, 0.f), h3b = fmaxf(lc[q].y + rc2.y, 0.f);
                    unsigned hp, lp;
                    split_bf16x2(h3a, h3b, hp, lp);
                    sA[j*LDP + kk2] = make_uint2(hp, lp);
                    float u  = h1a*f42.x + h1b*f42.y;
                    float qq = h2a*f52.x + h2b*f52.y;
                    #pragma unroll
                    for (int o=16;o>=4;o>>=1){
                        u  += __shfl_xor_sync(0xffffffffu, u,  o);
                        qq += __shfl_xor_sync(0xffffffffu, qq, o);
                    }
                    if (lane < 4) sp[j*8 + wp*4 + lane] = make_float2(u, qq);
                }
            }
        }
        __syncthreads();   // sA + sp published (and sB copy on bi==0)

        // ---- Phase B: K=128 (8 kt), warp tile 32 rows x 32 cols ----
        float C[2][4][4];
        #pragma unroll
        for (int ml=0;ml<2;ml++)
            #pragma unroll
            for (int nt=0;nt<4;nt++)
                #pragma unroll
                for (int q=0;q<4;q++) C[ml][nt][q] = 0.f;

        #pragma unroll
        for (int kt=0; kt<8; kt++){
            int p0 = kt*8 + tig;
            uint2 A0[2], A1[2], A2[2], A3[2];
            #pragma unroll
            for (int ml=0; ml<2; ml++){
                int row = (mg*2+ml)*16 + gid;
                A0[ml] = sA[ row   *LDP + p0  ];
                A1[ml] = sA[(row+8)*LDP + p0  ];
                A2[ml] = sA[ row   *LDP + p0+4];
                A3[ml] = sA[(row+8)*LDP + p0+4];
            }
            #pragma unroll
            for (int nt=0; nt<4; nt++){
                int idx = (ng*4+nt)*256 + kt*32 + lane;
                uint2 BH = sBh[idx];
                uint2 BL = sBl[idx];
                #pragma unroll
                for (int ml=0; ml<2; ml++){
                    mma_bf16(C[ml][nt], A0[ml].x,A1[ml].x,A2[ml].x,A3[ml].x, BH.x, BH.y);
                    mma_bf16(C[ml][nt], A0[ml].x,A1[ml].x,A2[ml].x,A3[ml].x, BL.x, BL.y);
                    mma_bf16(C[ml][nt], A0[ml].y,A1[ml].y,A2[ml].y,A3[ml].y, BH.x, BH.y);
                }
            }
        }

        // ---- Phase C: per-row y^2 and y.v partials (warp's 32 cols) ----
        #pragma unroll
        for (int ml=0; ml<2; ml++){
            int rowA = (mg*2+ml)*16 + gid;
            int rowB = rowA + 8;
            float yyA=0.f, yvA=0.f, yyB=0.f, yvB=0.f;
            #pragma unroll
            for (int nt=0; nt<4; nt++){
                int col0 = cb + nt*8 + tig*2;
                float y0 = C[ml][nt][0] + b6v[nt][0];
                float y1 = C[ml][nt][1] + b6v[nt][1];
                float y2 = C[ml][nt][2] + b6v[nt][0];
                float y3 = C[ml][nt][3] + b6v[nt][1];
                float v0=0.f, v1=0.f, v2=0.f, v3=0.f;
                if (rowA < MAXPV){
                    float2 vv = *reinterpret_cast<const float2*>(&g_vemb[(b*MAXPV+rowA)*ED + col0]);
                    v0 = vv.x; v1 = vv.y;
                }
                if (rowB < MAXPV){
                    float2 vv = *reinterpret_cast<const float2*>(&g_vemb[(b*MAXPV+rowB)*ED + col0]);
                    v2 = vv.x; v3 = vv.y;
                }
                yyA += y0*y0 + y1*y1;  yvA += y0*v0 + y1*v1;
                yyB += y2*y2 + y3*y3;  yvB += y2*v2 + y3*v3;
            }
            #pragma unroll
            for (int o=1;o<=2;o<<=1){
                yyA += __shfl_xor_sync(0xffffffffu, yyA, o);
                yvA += __shfl_xor_sync(0xffffffffu, yvA, o);
                yyB += __shfl_xor_sync(0xffffffffu, yyB, o);
                yvB += __shfl_xor_sync(0xffffffffu, yvB, o);
            }
            if (tig == 0){
                yred[rowA*4 + ng] = make_float2(yyA, yvA);
                yred[rowB*4 + ng] = make_float2(yyB, yvB);
            }
        }
        __syncthreads();   // yred published

        // ---- scoring (unnormalized) ----
        if (t < MAXPV){
            float s1d=0.f, pd=0.f, yn2=0.f, ydv=0.f;
            #pragma unroll
            for (int i=0;i<8;i++){
                float2 q1 = sp[t*8 + i];
                s1d += q1.x; pd += q1.y;
            }
            #pragma unroll
            for (int i=0;i<4;i++){
                float2 q2 = yred[t*4 + i];
                yn2 += q2.x; ydv += q2.y;
            }
            float s1 = 1.f/(1.f+expf(-(s1d+fb4)));
            float p  = 1.f/(1.f+expf(-(pd +fb5)));
            float yn = sqrtf(yn2);
            float cosv = ydv / fmaxf(yn, 1e-8f);   // v_emb unit-norm; gv = y/||y||
            float s2 = 0.5f*cosv + 0.5f;
            float sc = p + (1.f-p)*s2;
            sc = (samemask[b*MAXPV+t]==1) ? (s1*sc) : (1.f - s1);
            sc *= (float)padmask[b*MAXPV+t];
            if (!(s1 > 0.5f)) sc = 0.f;
            scj[t] = sc;
        }
        __syncthreads();
        if (t < 32){
            float s = scj[t];
            if (t + 32 < MAXPV) s += scj[t+32];
            #pragma unroll
            for (int o=16;o>0;o>>=1) s += __shfl_xor_sync(0xffffffffu, s, o);
            if (t==0) g_scores[b*RULENUM + r] = s;
        }
        __syncthreads();   // protect scj/sp/sA before next b
    }
}

// ---------------- kernel 5: deterministic finalize ---------------------------
// pooled[b] = max_r scores[b][r] / rulemask[r]   (division deferred here)
__global__ void finalize_kernel(float* __restrict__ out, int out_size)
{
    int tid = threadIdx.x, lane = tid&31, w = tid>>5;  // 256 threads, 8 warps
    __shared__ float rmi[RULENUM];
    rmi[tid] = 1.f / g_rulemask[tid];

    float rg = g_regpart[tid];
    #pragma unroll
    for (int o=16;o>0;o>>=1) rg += __shfl_xor_sync(0xffffffffu, rg, o);
    __shared__ float rs[8];
    if (lane==0) rs[w] = rg;
    __syncthreads();
    if (tid==0 && out_size > BATCH){
        float t=0.f;
        #pragma unroll
        for (int i=0;i<8;i++) t += rs[i];
        out[BATCH] = t / (float)(RULENUM*RULENUM);
    }
    #pragma unroll
    for (int q=0;q<4;q++){
        int b = w*4 + q;
        float m = -1e30f;
        for (int c=lane;c<RULENUM;c+=32)
            m = fmaxf(m, g_scores[b*RULENUM+c] * rmi[c]);
        #pragma unroll
        for (int o=16;o>0;o>>=1) m = fmaxf(m, __shfl_xor_sync(0xffffffffu, m, o));
        if (lane==0 && b < out_size) out[b] = m;
    }
}

// ---------------- launch -----------------------------------------------------
extern "C" void kernel_launch(void* const* d_in, const int* in_sizes, int n_in,
                              void* d_out, int out_size)
{
    const int*   prop = (const int*)d_in[0];
    const int*   val  = (const int*)d_in[1];
    const int*   same = (const int*)d_in[2];
    const int*   pad  = (const int*)d_in[3];
    const float* rule = (const float*)d_in[4];
    const float* ent  = (const float*)d_in[5];
    const float* fc1w = (const float*)d_in[6];
    const float* fc1b = (const float*)d_in[7];
    const float* fc2w = (const float*)d_in[8];
    const float* fc2b = (const float*)d_in[9];
    const float* fc3w = (const float*)d_in[10];
    const float* fc3b = (const float*)d_in[11];
    const float* fc4w = (const float*)d_in[12];
    const float* fc4b = (const float*)d_in[13];
    const float* fc5w = (const float*)d_in[14];
    const float* fc5b = (const float*)d_in[15];
    const float* fc6w = (const float*)d_in[16];
    const float* fc6b = (const float*)d_in[17];

    cudaFuncSetAttribute(main_kernel,
                         cudaFuncAttributeMaxDynamicSharedMemorySize, SMEM_BYTES);

    norm_gather_kernel<<<480, 256>>>(prop, val, ent, rule, fc6w);
    small_gemm_kernel<<<364, 128>>>(fc1w, fc1b, fc2w, fc2b, fc3w, fc3b);
    main_kernel<<<dim3(RULENUM, 9), 256, SMEM_BYTES>>>(same, pad, fc4w, fc4b,
                                                       fc5w, fc5b, fc6b);
    finalize_kernel<<<1, 256>>>((float*)d_out, out_size);
}